// round 2
// baseline (speedup 1.0000x reference)
#include <cuda_runtime.h>
#include <math.h>

#define NM 2
#define NB 32
#define NL 512
#define NS 26
#define NQ 512
#define HMM_EPS 1e-16f
#define NTOT (NM*NB*NL*NQ)   // 16,777,216

// ---- scratch (no allocs allowed: __device__ globals) ----
__device__ float g_A [NM*NQ*NQ];   // A row-major  [m][k][q]   (fwd: out q, reduce k)
__device__ float g_AT[NM*NQ*NQ];   // A^T row-major [m][k][j]  (bwd: out j, reduce k)
__device__ float g_Bt[NM*NS*NQ];   // B transposed [m][s][q]
__device__ float g_init[NM*NQ];
__device__ float g_E    [NTOT];    // em + eps (linear), [m][b][l][q]
__device__ float g_alpha[NTOT];    // normalized linear alpha
__device__ float g_beta [NTOT];    // normalized linear beta
__device__ float g_Sa[NM*NB*NL];   // cumulative log-scale (fwd)
__device__ float g_Sb[NM*NB*NL];   // cumulative log-scale (bwd)

// ============================================================
// Prep: row softmax of transition (writes A and A^T) and init.
// blocks 0..1023: transition rows; blocks 1024..1025: init rows.
// ============================================================
__global__ void prep_rows_kernel(const float* __restrict__ trans,
                                 const float* __restrict__ initl) {
    int bid = blockIdx.x;
    int t = threadIdx.x;
    int lane = t & 31, warp = t >> 5;
    __shared__ float red[16];
    __shared__ float s_max, s_inv;

    const float* row;
    if (bid < NM*NQ) row = trans + (size_t)bid * NQ;
    else             row = initl + (size_t)(bid - NM*NQ) * NQ;
    float x = row[t];

    // block max
    float v = x;
    #pragma unroll
    for (int o = 16; o; o >>= 1) v = fmaxf(v, __shfl_xor_sync(0xffffffffu, v, o));
    if (lane == 0) red[warp] = v;
    __syncthreads();
    if (t == 0) {
        float m = red[0];
        #pragma unroll
        for (int i = 1; i < 16; i++) m = fmaxf(m, red[i]);
        s_max = m;
    }
    __syncthreads();

    float e = expf(x - s_max);

    // block sum
    v = e;
    #pragma unroll
    for (int o = 16; o; o >>= 1) v += __shfl_xor_sync(0xffffffffu, v, o);
    if (lane == 0) red[warp] = v;
    __syncthreads();
    if (t == 0) {
        float s = 0.f;
        #pragma unroll
        for (int i = 0; i < 16; i++) s += red[i];
        s_inv = 1.0f / s;
    }
    __syncthreads();

    float p = e * s_inv;
    if (bid < NM*NQ) {
        int m = bid >> 9, r = bid & 511;
        g_A [(size_t)bid * NQ + t] = p;
        g_AT[((size_t)m * NQ + t) * NQ + r] = p;
    } else {
        g_init[(bid - NM*NQ) * NQ + t] = p;
    }
}

// ============================================================
// Prep: B = softmax(emission, axis=s), stored transposed [m][s][q].
// One warp per (m,q) row of length 26.
// ============================================================
__global__ void prep_B_kernel(const float* __restrict__ emis) {
    int gw = (blockIdx.x * blockDim.x + threadIdx.x) >> 5;
    int lane = threadIdx.x & 31;
    if (gw >= NM*NQ) return;
    float x = (lane < NS) ? emis[(size_t)gw * NS + lane] : -3.4e38f;
    float v = x;
    #pragma unroll
    for (int o = 16; o; o >>= 1) v = fmaxf(v, __shfl_xor_sync(0xffffffffu, v, o));
    float mx = v;
    float e = (lane < NS) ? expf(x - mx) : 0.0f;
    v = e;
    #pragma unroll
    for (int o = 16; o; o >>= 1) v += __shfl_xor_sync(0xffffffffu, v, o);
    if (lane < NS) {
        int m = gw >> 9, q = gw & 511;
        g_Bt[((size_t)m * NS + lane) * NQ + q] = e / v;
    }
}

// ============================================================
// E = inputs @ B^T + eps. 16 (m,b,l)-rows per block, 512 threads.
// Bt slice (53KB/model) stays hot in L1.
// ============================================================
__global__ void em_kernel(const float* __restrict__ inp) {
    __shared__ float srow[NS];
    int t = threadIdx.x;
    int row0 = blockIdx.x * 16;
    int m = row0 / (NB*NL);
    const float* __restrict__ Bt = g_Bt + (size_t)m * NS * NQ;
    for (int r = 0; r < 16; r++) {
        int row = row0 + r;
        __syncthreads();
        if (t < NS) srow[t] = inp[(size_t)row * NS + t];
        __syncthreads();
        float acc = HMM_EPS;
        #pragma unroll
        for (int s = 0; s < NS; s++)
            acc = fmaf(srow[s], __ldg(&Bt[s * NQ + t]), acc);
        g_E[(size_t)row * NQ + t] = acc;
    }
}

// ============================================================
// Shared reduce + normalize + store for one step (two batches).
// ============================================================
__device__ __forceinline__ void reduce_norm_store(
    float w0, float w1, int l,
    float2* vab, float* red, float* cinv,
    float& S0, float& S1,
    float* __restrict__ out0, float* __restrict__ out1,
    float* __restrict__ Sout0, float* __restrict__ Sout1)
{
    int t = threadIdx.x, lane = t & 31, warp = t >> 5;
    float s0 = w0, s1 = w1;
    #pragma unroll
    for (int o = 16; o; o >>= 1) {
        s0 += __shfl_xor_sync(0xffffffffu, s0, o);
        s1 += __shfl_xor_sync(0xffffffffu, s1, o);
    }
    if (lane == 0) { red[warp] = s0; red[16 + warp] = s1; }
    __syncthreads();
    if (t == 0) {
        float c0 = 0.f, c1 = 0.f;
        #pragma unroll
        for (int i = 0; i < 16; i++) { c0 += red[i]; c1 += red[16 + i]; }
        cinv[0] = 1.0f / c0; cinv[1] = 1.0f / c1;
        S0 += __logf(c0); S1 += __logf(c1);
        Sout0[l] = S0; Sout1[l] = S1;
    }
    __syncthreads();
    float n0 = w0 * cinv[0], n1 = w1 * cinv[1];
    vab[t] = make_float2(n0, n1);
    out0[(size_t)l * NQ + t] = n0;
    out1[(size_t)l * NQ + t] = n1;
    __syncthreads();
}

// ============================================================
// Fused forward/backward scaled recursions.
// 64 CTAs: dir(2) x model(2) x batch-pair(16). 512 threads = one
// output column each; 2 batches share every A load.
// ============================================================
__global__ void fb_kernel() {
    __shared__ float2 vab[NQ];
    __shared__ float2 uab[NQ];
    __shared__ float red[32];
    __shared__ float cinv[2];

    int bx  = blockIdx.x;
    int dir = bx >> 5;
    int m   = (bx >> 4) & 1;
    int pr  = bx & 15;
    int b0  = pr * 2, b1 = b0 + 1;
    int t   = threadIdx.x;

    const float* __restrict__ Amat = (dir == 0 ? g_A : g_AT) + (size_t)m * NQ * NQ;
    float* stv = (dir == 0 ? g_alpha : g_beta);
    float* Ss  = (dir == 0 ? g_Sa    : g_Sb);

    size_t r0 = (size_t)(m * NB + b0) * NL;
    size_t r1 = (size_t)(m * NB + b1) * NL;
    float* out0 = stv + r0 * NQ;
    float* out1 = stv + r1 * NQ;
    const float* __restrict__ E0 = g_E + r0 * NQ;
    const float* __restrict__ E1 = g_E + r1 * NQ;
    float* S0p = Ss + r0;
    float* S1p = Ss + r1;

    float S0 = 0.f, S1 = 0.f;
    const float* __restrict__ ap = Amat + t;

    if (dir == 0) {
        // alpha_0 = init * E_0, then alpha_l = (alpha @ A) * E_l
        float ini = g_init[m * NQ + t];
        float w0 = ini * E0[t];
        float w1 = ini * E1[t];
        reduce_norm_store(w0, w1, 0, vab, red, cinv, S0, S1, out0, out1, S0p, S1p);
        for (int l = 1; l < NL; l++) {
            float a0 = 0.f, a1 = 0.f;
            #pragma unroll 8
            for (int k = 0; k < NQ; k++) {
                float a = ap[(size_t)k * NQ];
                float2 v = vab[k];
                a0 = fmaf(a, v.x, a0);
                a1 = fmaf(a, v.y, a1);
            }
            float w0s = a0 * E0[(size_t)l * NQ + t];
            float w1s = a1 * E1[(size_t)l * NQ + t];
            reduce_norm_store(w0s, w1s, l, vab, red, cinv, S0, S1, out0, out1, S0p, S1p);
        }
    } else {
        // beta_{L-1} = 1, then beta_l = A @ (E_{l+1} * beta_{l+1})
        vab[t] = make_float2(1.f, 1.f);
        out0[(size_t)(NL-1) * NQ + t] = 1.f;
        out1[(size_t)(NL-1) * NQ + t] = 1.f;
        if (t == 0) { S0p[NL-1] = 0.f; S1p[NL-1] = 0.f; }
        __syncthreads();
        for (int l = NL - 2; l >= 0; l--) {
            float2 v = vab[t];
            uab[t] = make_float2(v.x * E0[(size_t)(l+1) * NQ + t],
                                 v.y * E1[(size_t)(l+1) * NQ + t]);
            __syncthreads();
            float a0 = 0.f, a1 = 0.f;
            #pragma unroll 8
            for (int k = 0; k < NQ; k++) {
                float a = ap[(size_t)k * NQ];
                float2 u = uab[k];
                a0 = fmaf(a, u.x, a0);
                a1 = fmaf(a, u.y, a1);
            }
            reduce_norm_store(a0, a1, l, vab, red, cinv, S0, S1, out0, out1, S0p, S1p);
        }
    }
}

// ============================================================
// posterior = log(alpha) + log(beta) + Sa + Sb - loglik
// loglik[m,b] = Sa[m,b,L-1]  (alpha normalized to sum 1 each step)
// ============================================================
__global__ void post_kernel(float* __restrict__ out) {
    int i = blockIdx.x * NQ + threadIdx.x;     // < NTOT
    int row = i >> 9;                          // (m,b,l)
    int mb  = row >> 9;                        // (m,b)
    float ll = g_Sa[mb * NL + (NL - 1)];
    out[i] = __logf(g_alpha[i]) + __logf(g_beta[i]) + g_Sa[row] + g_Sb[row] - ll;
    if (i < NM*NB) out[NTOT + i] = g_Sa[i * NL + (NL - 1)];
}

extern "C" void kernel_launch(void* const* d_in, const int* in_sizes, int n_in,
                              void* d_out, int out_size) {
    const float* inputs = (const float*)d_in[0];   // (2,32,512,26)
    const float* trans  = (const float*)d_in[1];   // (2,512,512)
    const float* emis   = (const float*)d_in[2];   // (2,512,26)
    const float* initl  = (const float*)d_in[3];   // (2,512)
    float* out = (float*)d_out;                    // posterior ++ loglik

    prep_rows_kernel<<<NM*NQ + NM, NQ>>>(trans, initl);
    prep_B_kernel<<<(NM*NQ*32 + 255)/256, 256>>>(emis);
    em_kernel<<<NM*NB*NL/16, NQ>>>(inputs);
    fb_kernel<<<64, NQ>>>();
    post_kernel<<<NTOT/NQ, NQ>>>(out);
}

// round 3
// speedup vs baseline: 4.3281x; 4.3281x over previous
#include <cuda_runtime.h>
#include <math.h>

#define NM 2
#define NB 32
#define NL 512
#define NS 26
#define NQ 512
#define HMM_EPS 1e-16f
#define NTOT (NM*NB*NL*NQ)   // 16,777,216

// ---- scratch (no allocs allowed: __device__ globals) ----
__device__ float4 g_A4 [NM*NQ*(NQ/4)];  // A row-major  [m][k][q/4] (fwd)
__device__ float4 g_AT4[NM*NQ*(NQ/4)];  // A^T row-major [m][k][j/4] (bwd)
__device__ float  g_Bt[NM*NS*NQ];       // B transposed [m][s][q]
__device__ float  g_init[NM*NQ];
__device__ float  g_E    [NTOT];        // em + eps (linear), [m][b][l][q]
__device__ float  g_alpha[NTOT];        // normalized linear alpha
__device__ float  g_beta [NTOT];        // normalized linear beta
__device__ float  g_Sa[NM*NB*NL];       // cumulative log-scale (fwd)
__device__ float  g_Sb[NM*NB*NL];       // cumulative log-scale (bwd)

// ============================================================
// Prep: row softmax of transition (writes A and A^T) and init.
// ============================================================
__global__ void prep_rows_kernel(const float* __restrict__ trans,
                                 const float* __restrict__ initl) {
    int bid = blockIdx.x;
    int t = threadIdx.x;
    int lane = t & 31, warp = t >> 5;
    __shared__ float red[16];
    __shared__ float s_max, s_inv;

    const float* row;
    if (bid < NM*NQ) row = trans + (size_t)bid * NQ;
    else             row = initl + (size_t)(bid - NM*NQ) * NQ;
    float x = row[t];

    float v = x;
    #pragma unroll
    for (int o = 16; o; o >>= 1) v = fmaxf(v, __shfl_xor_sync(0xffffffffu, v, o));
    if (lane == 0) red[warp] = v;
    __syncthreads();
    if (t == 0) {
        float m = red[0];
        #pragma unroll
        for (int i = 1; i < 16; i++) m = fmaxf(m, red[i]);
        s_max = m;
    }
    __syncthreads();

    float e = expf(x - s_max);

    v = e;
    #pragma unroll
    for (int o = 16; o; o >>= 1) v += __shfl_xor_sync(0xffffffffu, v, o);
    if (lane == 0) red[warp] = v;
    __syncthreads();
    if (t == 0) {
        float s = 0.f;
        #pragma unroll
        for (int i = 0; i < 16; i++) s += red[i];
        s_inv = 1.0f / s;
    }
    __syncthreads();

    float p = e * s_inv;
    if (bid < NM*NQ) {
        int m = bid >> 9, r = bid & 511;
        ((float*)g_A4) [(size_t)bid * NQ + t] = p;
        ((float*)g_AT4)[((size_t)m * NQ + t) * NQ + r] = p;
    } else {
        g_init[(bid - NM*NQ) * NQ + t] = p;
    }
}

// ============================================================
// Prep: B = softmax(emission, axis=s), stored transposed [m][s][q].
// ============================================================
__global__ void prep_B_kernel(const float* __restrict__ emis) {
    int gw = (blockIdx.x * blockDim.x + threadIdx.x) >> 5;
    int lane = threadIdx.x & 31;
    if (gw >= NM*NQ) return;
    float x = (lane < NS) ? emis[(size_t)gw * NS + lane] : -3.4e38f;
    float v = x;
    #pragma unroll
    for (int o = 16; o; o >>= 1) v = fmaxf(v, __shfl_xor_sync(0xffffffffu, v, o));
    float mx = v;
    float e = (lane < NS) ? expf(x - mx) : 0.0f;
    v = e;
    #pragma unroll
    for (int o = 16; o; o >>= 1) v += __shfl_xor_sync(0xffffffffu, v, o);
    if (lane < NS) {
        int m = gw >> 9, q = gw & 511;
        g_Bt[((size_t)m * NS + lane) * NQ + q] = e / v;
    }
}

// ============================================================
// E = inputs @ B^T + eps.
// ============================================================
__global__ void em_kernel(const float* __restrict__ inp) {
    __shared__ float srow[NS];
    int t = threadIdx.x;
    int row0 = blockIdx.x * 16;
    int m = row0 / (NB*NL);
    const float* __restrict__ Bt = g_Bt + (size_t)m * NS * NQ;
    for (int r = 0; r < 16; r++) {
        int row = row0 + r;
        __syncthreads();
        if (t < NS) srow[t] = inp[(size_t)row * NS + t];
        __syncthreads();
        float acc = HMM_EPS;
        #pragma unroll
        for (int s = 0; s < NS; s++)
            acc = fmaf(srow[s], __ldg(&Bt[s * NQ + t]), acc);
        g_E[(size_t)row * NQ + t] = acc;
    }
}

// ============================================================
// Fused forward/backward scaled recursions.
// 64 CTAs: dir(2) x model(2) x batch-pair(16). 512 threads as
// (kg in [0,4)) x (qg in [0,128)): each thread accumulates 4
// output columns over a 128-row k-slice with LDG.128 A loads.
// ============================================================
__global__ void __launch_bounds__(512, 1) fb_kernel() {
    __shared__ __align__(16) float2 vab[NQ];   // normalized state (b0,b1)
    __shared__ __align__(16) float2 uab[NQ];   // bwd E-weighted state
    __shared__ float2 part[3*NQ];              // partials from kg=1..3
    __shared__ float2 red[4];
    __shared__ float2 cinv2;

    int bx  = blockIdx.x;
    int dir = bx >> 5;
    int m   = (bx >> 4) & 1;
    int pr  = bx & 15;
    int b0  = pr * 2, b1 = b0 + 1;
    int t   = threadIdx.x;
    int kg  = t >> 7;           // 0..3 : k-slice
    int qg  = t & 127;          // 0..127 : q quad
    int q0  = qg << 2;
    int lane = t & 31;

    const float4* __restrict__ Abase =
        (dir == 0 ? g_A4 : g_AT4) + (size_t)m * NQ * (NQ/4);
    float* stv = (dir == 0 ? g_alpha : g_beta);
    float* Ss  = (dir == 0 ? g_Sa    : g_Sb);

    size_t r0 = (size_t)(m * NB + b0) * NL;
    size_t r1 = (size_t)(m * NB + b1) * NL;
    float* out0 = stv + r0 * NQ;
    float* out1 = stv + r1 * NQ;
    const float* __restrict__ E0 = g_E + r0 * NQ;
    const float* __restrict__ E1 = g_E + r1 * NQ;
    float* S0p = Ss + r0;
    float* S1p = Ss + r1;

    float S0 = 0.f, S1 = 0.f;   // only thread 0's copy is live

    // ---- per-step lambdas (all threads execute; ifs internal) ----
    // matvec over shared vector sv (float2[NQ], 16B aligned)
    auto matvec = [&](const float2* sv, float2 acc[4]) {
        const float4* sv4 = (const float4*)sv;
        const float4* __restrict__ ap = Abase + (size_t)(kg * 128) * 128 + qg;
        #pragma unroll 4
        for (int k2 = 0; k2 < 64; k2++) {
            float4 vv = sv4[kg * 64 + k2];
            float4 a0 = __ldg(ap + (size_t)(2*k2    ) * 128);
            float4 a1 = __ldg(ap + (size_t)(2*k2 + 1) * 128);
            acc[0].x = fmaf(a0.x, vv.x, acc[0].x);
            acc[0].y = fmaf(a0.x, vv.y, acc[0].y);
            acc[1].x = fmaf(a0.y, vv.x, acc[1].x);
            acc[1].y = fmaf(a0.y, vv.y, acc[1].y);
            acc[2].x = fmaf(a0.z, vv.x, acc[2].x);
            acc[2].y = fmaf(a0.z, vv.y, acc[2].y);
            acc[3].x = fmaf(a0.w, vv.x, acc[3].x);
            acc[3].y = fmaf(a0.w, vv.y, acc[3].y);
            acc[0].x = fmaf(a1.x, vv.z, acc[0].x);
            acc[0].y = fmaf(a1.x, vv.w, acc[0].y);
            acc[1].x = fmaf(a1.y, vv.z, acc[1].x);
            acc[1].y = fmaf(a1.y, vv.w, acc[1].y);
            acc[2].x = fmaf(a1.z, vv.z, acc[2].x);
            acc[2].y = fmaf(a1.z, vv.w, acc[2].y);
            acc[3].x = fmaf(a1.w, vv.z, acc[3].x);
            acc[3].y = fmaf(a1.w, vv.w, acc[3].y);
        }
    };

    // reduce across kg, optional E-multiply, normalize, store step l
    auto finish = [&](float2 acc[4], int l, bool mulE) {
        if (kg) {
            #pragma unroll
            for (int i = 0; i < 4; i++) part[(kg-1)*NQ + q0 + i] = acc[i];
        }
        __syncthreads();
        float2 w[4];
        if (kg == 0) {
            float4 e0q, e1q;
            if (mulE) {
                e0q = *(const float4*)(E0 + (size_t)l * NQ + q0);
                e1q = *(const float4*)(E1 + (size_t)l * NQ + q0);
            }
            #pragma unroll
            for (int i = 0; i < 4; i++) {
                float2 s = acc[i];
                float2 p0 = part[q0 + i], p1 = part[NQ + q0 + i], p2 = part[2*NQ + q0 + i];
                s.x += p0.x + p1.x + p2.x;
                s.y += p0.y + p1.y + p2.y;
                w[i] = s;
            }
            if (mulE) {
                w[0].x *= e0q.x; w[1].x *= e0q.y; w[2].x *= e0q.z; w[3].x *= e0q.w;
                w[0].y *= e1q.x; w[1].y *= e1q.y; w[2].y *= e1q.z; w[3].y *= e1q.w;
            }
            float2 ps;
            ps.x = w[0].x + w[1].x + w[2].x + w[3].x;
            ps.y = w[0].y + w[1].y + w[2].y + w[3].y;
            #pragma unroll
            for (int o = 16; o; o >>= 1) {
                ps.x += __shfl_xor_sync(0xffffffffu, ps.x, o);
                ps.y += __shfl_xor_sync(0xffffffffu, ps.y, o);
            }
            if (lane == 0) red[t >> 5] = ps;
        }
        __syncthreads();
        if (t == 0) {
            float c0 = red[0].x + red[1].x + red[2].x + red[3].x;
            float c1 = red[0].y + red[1].y + red[2].y + red[3].y;
            cinv2 = make_float2(1.0f / c0, 1.0f / c1);
            S0 += __logf(c0); S1 += __logf(c1);
            S0p[l] = S0; S1p[l] = S1;
        }
        __syncthreads();
        if (kg == 0) {
            float2 ci = cinv2;
            #pragma unroll
            for (int i = 0; i < 4; i++) {
                float2 n = make_float2(w[i].x * ci.x, w[i].y * ci.y);
                vab[q0 + i] = n;
                out0[(size_t)l * NQ + q0 + i] = n.x;
                out1[(size_t)l * NQ + q0 + i] = n.y;
            }
        }
        __syncthreads();
    };

    if (dir == 0) {
        // alpha_0 = init * E_0
        {
            float2 w4[4];
            if (kg == 0) {
                float4 ini = *(const float4*)(g_init + m * NQ + q0);
                float4 e0q = *(const float4*)(E0 + q0);
                float4 e1q = *(const float4*)(E1 + q0);
                w4[0] = make_float2(ini.x * e0q.x, ini.x * e1q.x);
                w4[1] = make_float2(ini.y * e0q.y, ini.y * e1q.y);
                w4[2] = make_float2(ini.z * e0q.z, ini.z * e1q.z);
                w4[3] = make_float2(ini.w * e0q.w, ini.w * e1q.w);
            } else {
                #pragma unroll
                for (int i = 0; i < 4; i++) w4[i] = make_float2(0.f, 0.f);
            }
            // reuse finish's reduce path: non-kg0 partials are zero
            finish(w4, 0, false);
        }
        for (int l = 1; l < NL; l++) {
            float2 acc[4] = {{0,0},{0,0},{0,0},{0,0}};
            matvec(vab, acc);
            finish(acc, l, true);
        }
    } else {
        // beta_{L-1} = 1
        {
            float2 one = make_float2(1.f, 1.f);
            vab[t] = one;
            if (kg == 0) {
                #pragma unroll
                for (int i = 0; i < 4; i++) {
                    out0[(size_t)(NL-1) * NQ + q0 + i] = 1.f;
                    out1[(size_t)(NL-1) * NQ + q0 + i] = 1.f;
                }
            }
            if (t == 0) { S0p[NL-1] = 0.f; S1p[NL-1] = 0.f; }
            __syncthreads();
        }
        for (int l = NL - 2; l >= 0; l--) {
            float2 v = vab[t];
            uab[t] = make_float2(v.x * E0[(size_t)(l+1) * NQ + t],
                                 v.y * E1[(size_t)(l+1) * NQ + t]);
            __syncthreads();
            float2 acc[4] = {{0,0},{0,0},{0,0},{0,0}};
            matvec(uab, acc);
            finish(acc, l, false);
        }
    }
}

// ============================================================
// posterior = log(alpha) + log(beta) + Sa + Sb - loglik
// ============================================================
__global__ void post_kernel(float* __restrict__ out) {
    int i = blockIdx.x * NQ + threadIdx.x;     // < NTOT
    int row = i >> 9;                          // (m,b,l)
    int mb  = row >> 9;                        // (m,b)
    float ll = g_Sa[mb * NL + (NL - 1)];
    out[i] = __logf(g_alpha[i]) + __logf(g_beta[i]) + g_Sa[row] + g_Sb[row] - ll;
    if (i < NM*NB) out[NTOT + i] = g_Sa[i * NL + (NL - 1)];
}

extern "C" void kernel_launch(void* const* d_in, const int* in_sizes, int n_in,
                              void* d_out, int out_size) {
    const float* inputs = (const float*)d_in[0];   // (2,32,512,26)
    const float* trans  = (const float*)d_in[1];   // (2,512,512)
    const float* emis   = (const float*)d_in[2];   // (2,512,26)
    const float* initl  = (const float*)d_in[3];   // (2,512)
    float* out = (float*)d_out;                    // posterior ++ loglik

    prep_rows_kernel<<<NM*NQ + NM, NQ>>>(trans, initl);
    prep_B_kernel<<<(NM*NQ*32 + 255)/256, 256>>>(emis);
    em_kernel<<<NM*NB*NL/16, NQ>>>(inputs);
    fb_kernel<<<64, NQ>>>();
    post_kernel<<<NTOT/NQ, NQ>>>(out);
}

// round 6
// speedup vs baseline: 5.5993x; 1.2937x over previous
#include <cuda_runtime.h>
#include <cuda_bf16.h>
#include <math.h>
#include <stdint.h>

#define NM 2
#define NB 32
#define NL 512
#define NS 26
#define NQ 512
#define HMM_EPS 1e-16f
#define NTOT (NM*NB*NL*NQ)   // 16,777,216

typedef unsigned long long ull;

// ---- scratch (no allocs allowed: __device__ globals) ----
__device__ __nv_bfloat16 g_Ah [NM*NQ*NQ]; // A  bf16 [m][k][q]  (fwd)
__device__ __nv_bfloat16 g_ATh[NM*NQ*NQ]; // A^T bf16 [m][k][j] (bwd)
__device__ float  g_Bt[NM*NS*NQ];         // B transposed [m][s][q]
__device__ float  g_init[NM*NQ];
__device__ float  g_E    [NTOT];          // em + eps (linear), [m][b][l][q]
__device__ float  g_alpha[NTOT];          // normalized linear alpha
__device__ float  g_beta [NTOT];          // normalized linear beta
__device__ float  g_Sa[NM*NB*NL];         // cumulative log-scale (fwd)
__device__ float  g_Sb[NM*NB*NL];         // cumulative log-scale (bwd)

// ---- packed f32x2 helpers ----
#define FMA2(d, a, b) asm("fma.rn.f32x2 %0, %1, %2, %0;" : "+l"(d) : "l"(a), "l"(b))

// two bf16 (packed in one u32, lo=q0 hi=q1) -> f32x2 pair (q0,q1)
__device__ __forceinline__ ull bf2f2(uint32_t w) {
    ull r;
    asm("mov.b64 %0, {%1, %2};" : "=l"(r) : "r"(w << 16), "r"(w & 0xFFFF0000u));
    return r;
}
__device__ __forceinline__ float2 lohi(ull p) {
    float lo, hi;
    asm("mov.b64 {%0, %1}, %2;" : "=f"(lo), "=f"(hi) : "l"(p));
    return make_float2(lo, hi);
}
// load float4 (v0,v0,v1,v1) from shared as two f32x2 operands
__device__ __forceinline__ void lds_y(uint32_t addr, ull& y0, ull& y1) {
    asm volatile("{\n\t.reg .b32 a,b,c,d;\n\t"
                 "ld.shared.v4.b32 {a,b,c,d}, [%2];\n\t"
                 "mov.b64 %0, {a,b};\n\t"
                 "mov.b64 %1, {c,d};\n\t}"
                 : "=l"(y0), "=l"(y1) : "r"(addr));
}
__device__ __forceinline__ uint32_t smem_u32(const void* p) {
    uint32_t a;
    asm("{ .reg .u64 t; cvta.to.shared.u64 t, %1; cvt.u32.u64 %0, t; }"
        : "=r"(a) : "l"(p));
    return a;
}

// ============================================================
// Prep: row softmax of transition (writes bf16 A and A^T) + init.
// ============================================================
__global__ void prep_rows_kernel(const float* __restrict__ trans,
                                 const float* __restrict__ initl) {
    int bid = blockIdx.x;
    int t = threadIdx.x;
    int lane = t & 31, warp = t >> 5;
    __shared__ float red[16];
    __shared__ float s_max, s_inv;

    const float* row;
    if (bid < NM*NQ) row = trans + (size_t)bid * NQ;
    else             row = initl + (size_t)(bid - NM*NQ) * NQ;
    float x = row[t];

    float v = x;
    #pragma unroll
    for (int o = 16; o; o >>= 1) v = fmaxf(v, __shfl_xor_sync(0xffffffffu, v, o));
    if (lane == 0) red[warp] = v;
    __syncthreads();
    if (t == 0) {
        float m = red[0];
        #pragma unroll
        for (int i = 1; i < 16; i++) m = fmaxf(m, red[i]);
        s_max = m;
    }
    __syncthreads();

    float e = expf(x - s_max);

    v = e;
    #pragma unroll
    for (int o = 16; o; o >>= 1) v += __shfl_xor_sync(0xffffffffu, v, o);
    if (lane == 0) red[warp] = v;
    __syncthreads();
    if (t == 0) {
        float s = 0.f;
        #pragma unroll
        for (int i = 0; i < 16; i++) s += red[i];
        s_inv = 1.0f / s;
    }
    __syncthreads();

    float p = e * s_inv;
    if (bid < NM*NQ) {
        int m = bid >> 9, r = bid & 511;
        __nv_bfloat16 h = __float2bfloat16(p);
        g_Ah [(size_t)bid * NQ + t] = h;
        g_ATh[((size_t)m * NQ + t) * NQ + r] = h;
    } else {
        g_init[(bid - NM*NQ) * NQ + t] = p;
    }
}

// ============================================================
// Prep: B = softmax(emission, axis=s), stored transposed [m][s][q].
// ============================================================
__global__ void prep_B_kernel(const float* __restrict__ emis) {
    int gw = (blockIdx.x * blockDim.x + threadIdx.x) >> 5;
    int lane = threadIdx.x & 31;
    if (gw >= NM*NQ) return;
    float x = (lane < NS) ? emis[(size_t)gw * NS + lane] : -3.4e38f;
    float v = x;
    #pragma unroll
    for (int o = 16; o; o >>= 1) v = fmaxf(v, __shfl_xor_sync(0xffffffffu, v, o));
    float mx = v;
    float e = (lane < NS) ? expf(x - mx) : 0.0f;
    v = e;
    #pragma unroll
    for (int o = 16; o; o >>= 1) v += __shfl_xor_sync(0xffffffffu, v, o);
    if (lane < NS) {
        int m = gw >> 9, q = gw & 511;
        g_Bt[((size_t)m * NS + lane) * NQ + q] = e / v;
    }
}

// ============================================================
// E = inputs @ B^T + eps.
// ============================================================
__global__ void em_kernel(const float* __restrict__ inp) {
    __shared__ float srow[NS];
    int t = threadIdx.x;
    int row0 = blockIdx.x * 16;
    int m = row0 / (NB*NL);
    const float* __restrict__ Bt = g_Bt + (size_t)m * NS * NQ;
    for (int r = 0; r < 16; r++) {
        int row = row0 + r;
        __syncthreads();
        if (t < NS) srow[t] = inp[(size_t)row * NS + t];
        __syncthreads();
        float acc = HMM_EPS;
        #pragma unroll
        for (int s = 0; s < NS; s++)
            acc = fmaf(srow[s], __ldg(&Bt[s * NQ + t]), acc);
        g_E[(size_t)row * NQ + t] = acc;
    }
}

// ============================================================
// Fused forward/backward scaled recursions, bf16 A, f32x2 math.
// 64 CTAs: dir(2) x model(2) x batch-pair(16). 512 threads:
//   matvec phase : (qoct = t&63) owns 8 q cols, (ks = t>>6) owns 64 k rows
//   reduce phase : thread t owns column q = t
// ============================================================
__global__ void __launch_bounds__(512, 1) fb_kernel() {
    __shared__ __align__(16) float4 vquad[NQ];     // (v0,v0,v1,v1) per k
    __shared__ __align__(16) float2 part[8][NQ];   // k-split partials (b0,b1)
    __shared__ float2 red2[16];

    int bx  = blockIdx.x;
    int dir = bx >> 5;
    int m   = (bx >> 4) & 1;
    int pr  = bx & 15;
    int b0  = pr * 2, b1 = b0 + 1;
    int t   = threadIdx.x;
    int qoct = t & 63;          // matvec: q-octet
    int ks   = t >> 6;          // matvec: k-slice 0..7
    int q    = t;               // reduce: owned column
    int lane = t & 31;

    const __nv_bfloat16* __restrict__ Abase =
        (dir == 0 ? g_Ah : g_ATh) + (size_t)m * NQ * NQ;
    const uint4* __restrict__ Ap0 =
        (const uint4*)(Abase + (size_t)(ks * 64) * NQ + qoct * 8);

    float* stv = (dir == 0 ? g_alpha : g_beta);
    float* Ss  = (dir == 0 ? g_Sa    : g_Sb);

    size_t r0 = (size_t)(m * NB + b0) * NL;
    size_t r1 = (size_t)(m * NB + b1) * NL;
    float* out0 = stv + r0 * NQ;
    float* out1 = stv + r1 * NQ;
    const float* __restrict__ E0 = g_E + r0 * NQ;
    const float* __restrict__ E1 = g_E + r1 * NQ;
    float* S0p = Ss + r0;
    float* S1p = Ss + r1;

    uint32_t vq_addr = smem_u32(&vquad[ks * 64]);  // this thread's k-slice base

    float S0 = 0.f, S1 = 0.f;   // live in thread 0 only

    // ---- matvec over vquad into partials; leaves part[][] filled ----
    auto matvec = [&]() {
        ull a0[4] = {0,0,0,0};   // batch0, q-pairs
        ull a1[4] = {0,0,0,0};   // batch1, q-pairs
        const uint4* __restrict__ ap = Ap0;
        #pragma unroll 8
        for (int k = 0; k < 64; k++) {
            ull y0, y1;
            lds_y(vq_addr + k * 16, y0, y1);
            uint4 w = __ldg(ap); ap += 64;   // next k row (512 bf16)
            ull x0 = bf2f2(w.x), x1 = bf2f2(w.y), x2 = bf2f2(w.z), x3 = bf2f2(w.w);
            FMA2(a0[0], x0, y0); FMA2(a0[1], x1, y0);
            FMA2(a0[2], x2, y0); FMA2(a0[3], x3, y0);
            FMA2(a1[0], x0, y1); FMA2(a1[1], x1, y1);
            FMA2(a1[2], x2, y1); FMA2(a1[3], x3, y1);
        }
        #pragma unroll
        for (int j = 0; j < 4; j++) {
            float2 pa = lohi(a0[j]);   // (w_{q2j,b0}, w_{q2j+1,b0})
            float2 pb = lohi(a1[j]);
            int qp = (qoct << 3) + (j << 1);
            *(float4*)&part[ks][qp] = make_float4(pa.x, pb.x, pa.y, pb.y);
        }
        __syncthreads();                 // partials visible
    };

    // ---- sum k-split partials for owned column q ----
    auto gather = [&](float& w0, float& w1) {
        w0 = 0.f; w1 = 0.f;
        #pragma unroll
        for (int s = 0; s < 8; s++) {
            float2 p = part[s][q];
            w0 += p.x; w1 += p.y;
        }
    };

    // ---- normalize w, store outputs, set vquad for next step ----
    // uE0/uE1: multiplier applied to n when writing vquad (bwd E-fold); 1 for fwd
    auto finish = [&](float w0, float w1, int l, float uE0, float uE1) {
        float s0 = w0, s1 = w1;
        #pragma unroll
        for (int o = 16; o; o >>= 1) {
            s0 += __shfl_xor_sync(0xffffffffu, s0, o);
            s1 += __shfl_xor_sync(0xffffffffu, s1, o);
        }
        if (lane == 0) red2[t >> 5] = make_float2(s0, s1);
        __syncthreads();
        float c0 = 0.f, c1 = 0.f;
        #pragma unroll
        for (int i = 0; i < 16; i++) { c0 += red2[i].x; c1 += red2[i].y; }
        if (t == 0) {
            S0 += __logf(c0); S1 += __logf(c1);
            S0p[l] = S0; S1p[l] = S1;
        }
        float n0 = w0 * __fdividef(1.f, c0);
        float n1 = w1 * __fdividef(1.f, c1);
        out0[(size_t)l * NQ + q] = n0;
        out1[(size_t)l * NQ + q] = n1;
        float u0 = n0 * uE0, u1 = n1 * uE1;
        vquad[q] = make_float4(u0, u0, u1, u1);
        __syncthreads();                 // vquad ready for next matvec
    };

    if (dir == 0) {
        // ---- forward: alpha_0 = init * E_0 ----
        {
            float ini = g_init[m * NQ + q];
            float w0 = ini * E0[q];
            float w1 = ini * E1[q];
            finish(w0, w1, 0, 1.f, 1.f);
        }
        for (int l = 1; l < NL; l++) {
            matvec();
            float e0 = E0[(size_t)l * NQ + q];
            float e1 = E1[(size_t)l * NQ + q];
            float w0, w1; gather(w0, w1);
            w0 *= e0; w1 *= e1;          // E folds into w before normalization
            finish(w0, w1, l, 1.f, 1.f);
        }
    } else {
        // ---- backward: beta_{L-1} = 1 ----
        {
            float e0 = E0[(size_t)(NL-1) * NQ + q];
            float e1 = E1[(size_t)(NL-1) * NQ + q];
            out0[(size_t)(NL-1) * NQ + q] = 1.f;
            out1[(size_t)(NL-1) * NQ + q] = 1.f;
            if (t == 0) { S0p[NL-1] = 0.f; S1p[NL-1] = 0.f; }
            vquad[q] = make_float4(e0, e0, e1, e1);   // E_{L-1} * 1
            __syncthreads();
        }
        for (int l = NL - 2; l >= 0; l--) {
            matvec();
            float e0 = E0[(size_t)l * NQ + q];   // E_l folds into NEXT operand
            float e1 = E1[(size_t)l * NQ + q];
            float w0, w1; gather(w0, w1);
            finish(w0, w1, l, e0, e1);
        }
    }
}

// ============================================================
// posterior = log(alpha) + log(beta) + Sa + Sb - loglik
// ============================================================
__global__ void post_kernel(float* __restrict__ out) {
    int i = blockIdx.x * NQ + threadIdx.x;     // < NTOT
    int row = i >> 9;                          // (m,b,l)
    int mb  = row >> 9;                        // (m,b)
    float ll = g_Sa[mb * NL + (NL - 1)];
    out[i] = __logf(g_alpha[i]) + __logf(g_beta[i]) + g_Sa[row] + g_Sb[row] - ll;
    if (i < NM*NB) out[NTOT + i] = g_Sa[i * NL + (NL - 1)];
}

extern "C" void kernel_launch(void* const* d_in, const int* in_sizes, int n_in,
                              void* d_out, int out_size) {
    const float* inputs = (const float*)d_in[0];   // (2,32,512,26)
    const float* trans  = (const float*)d_in[1];   // (2,512,512)
    const float* emis   = (const float*)d_in[2];   // (2,512,26)
    const float* initl  = (const float*)d_in[3];   // (2,512)
    float* out = (float*)d_out;                    // posterior ++ loglik

    prep_rows_kernel<<<NM*NQ + NM, NQ>>>(trans, initl);
    prep_B_kernel<<<(NM*NQ*32 + 255)/256, 256>>>(emis);
    em_kernel<<<NM*NB*NL/16, NQ>>>(inputs);
    fb_kernel<<<64, NQ>>>();
    post_kernel<<<NTOT/NQ, NQ>>>(out);
}